// round 6
// baseline (speedup 1.0000x reference)
#include <cuda_runtime.h>
#include <cuda_bf16.h>
#include <cstdint>
#include <cstddef>

// ---------------- problem constants ----------------
#define B_     64
#define NKV    8192
#define D      64      // INPUT_SIZE == SLOT_SIZE
#define NQ     8
#define C32    32      // NUM_HEADS * NUM_SLOTS
#define EPS_A  1e-8f
#define NCHUNK 32
#define TPC    256     // tokens per CTA
#define TT     64      // tokens per tile
#define NTILES (TPC / TT)   // 4

// smem strides
#define SXF 68         // fp32 input tile row stride (floats)
#define SXBU 36        // bf16 lnX tile row stride (u32 = bf16x2)
#define SATB 72        // attn^T row stride (bf16)
#define WFU 36         // WfoldT row stride (u32)

// ---------------- device scratch (no allocs allowed) ----------------
__device__ uint32_t g_wfoldu[B_ * C32 * 32];         // [b][c][e/2] bf16x2
__device__ float    g_part [B_ * NCHUNK * C32 * D];  // per-chunk S' partials
__device__ float    g_sap  [B_ * NCHUNK * C32];      // per-chunk colsum partials
__device__ float    g_slots[B_ * NQ * D];            // working slots
__device__ int      g_cnt  [B_];                     // arrival counters (self-resetting)

// ---------------- helpers ----------------
__device__ __forceinline__ uint32_t pack_bf16x2(float lo, float hi) {
    uint32_t r;
    asm("cvt.rn.bf16x2.f32 %0, %1, %2;" : "=r"(r) : "f"(hi), "f"(lo));
    return r;
}

__device__ __forceinline__ void mma16(float c[4],
                                      uint32_t a0, uint32_t a1, uint32_t a2, uint32_t a3,
                                      uint32_t b0, uint32_t b1) {
    asm volatile(
        "mma.sync.aligned.m16n8k16.row.col.f32.bf16.bf16.f32 "
        "{%0,%1,%2,%3},{%4,%5,%6,%7},{%8,%9},{%0,%1,%2,%3};"
        : "+f"(c[0]), "+f"(c[1]), "+f"(c[2]), "+f"(c[3])
        : "r"(a0), "r"(a1), "r"(a2), "r"(a3), "r"(b0), "r"(b1));
}

__device__ __forceinline__ void ldm_x4(uint32_t& r0, uint32_t& r1, uint32_t& r2, uint32_t& r3,
                                       uint32_t addr) {
    asm volatile("ldmatrix.sync.aligned.m8n8.x4.shared.b16 {%0,%1,%2,%3}, [%4];"
                 : "=r"(r0), "=r"(r1), "=r"(r2), "=r"(r3) : "r"(addr));
}
__device__ __forceinline__ void ldm_x4t(uint32_t& r0, uint32_t& r1, uint32_t& r2, uint32_t& r3,
                                        uint32_t addr) {
    asm volatile("ldmatrix.sync.aligned.m8n8.x4.trans.shared.b16 {%0,%1,%2,%3}, [%4];"
                 : "=r"(r0), "=r"(r1), "=r"(r2), "=r"(r3) : "r"(addr));
}

__device__ __forceinline__ void cp_async16(uint32_t smem_addr, const void* gptr) {
    asm volatile("cp.async.cg.shared.global [%0], [%1], 16;"
                 :: "r"(smem_addr), "l"(gptr));
}
__device__ __forceinline__ void cp_commit() { asm volatile("cp.async.commit_group;"); }
__device__ __forceinline__ void cp_wait0()  { asm volatile("cp.async.wait_group 0;"); }

__device__ __forceinline__ float sigm(float x) { return 1.f / (1.f + __expf(-x)); }

// =====================================================================
// Main fused kernel: one CTA per (batch, 256-token chunk), 128 threads.
// bf16 mma m16n8k16, ldmatrix fragments. The LAST-arriving CTA of each
// batch performs the full slot update (GRU+MLP[+Wfold]) in its tail.
// =====================================================================
__global__ void __launch_bounds__(128, 4)
vslot_main(const float* __restrict__ inputs,
           const float* __restrict__ lng_g,
           const float* __restrict__ lnb_g,
           float* __restrict__ vis,
           int last,
           const float* __restrict__ Wq,  const float* __restrict__ Wk,
           const float* __restrict__ Wv,
           const float* __restrict__ W_ih, const float* __restrict__ W_hh,
           const float* __restrict__ b_ih, const float* __restrict__ b_hh,
           const float* __restrict__ lns_g, const float* __restrict__ lns_b,
           const float* __restrict__ lnm_g, const float* __restrict__ lnm_b,
           const float* __restrict__ W1, const float* __restrict__ b1v,
           const float* __restrict__ W2, const float* __restrict__ b2v,
           float* __restrict__ out_slots)
{
    extern __shared__ float sm[];
    float*          sxf0 = sm;                                   // [64][68] f32
    float*          sxf1 = sxf0 + TT * SXF;                      // [64][68] f32
    uint32_t*       sxb  = (uint32_t*)(sxf1 + TT * SXF);         // [64][36] u32 (bf16x2 lnX)
    __nv_bfloat16*  satb = (__nv_bfloat16*)(sxb + TT * SXBU);    // [32][72] bf16 attn^T
    uint32_t*       wfT  = (uint32_t*)(satb + C32 * SATB);       // [32][36] u32 WfoldT
    float*          slng = (float*)(wfT + C32 * WFU);            // [64]
    float*          slnb = slng + 64;                            // [64]

    const int b     = blockIdx.x >> 5;
    const int chunk = blockIdx.x & 31;
    const int n0    = chunk * TPC;
    const int tid   = threadIdx.x;
    const int w     = tid >> 5;       // 0..3
    const int lane  = tid & 31;
    const int g     = lane >> 2;      // 0..7
    const int t     = lane & 3;       // 0..3
    const int r0    = w * 16 + g;     // mma rows r0, r0+8 (tokens in tile)

    // prologue loads
    for (int i = tid; i < C32 * 32; i += 128)
        wfT[(i >> 5) * WFU + (i & 31)] = g_wfoldu[b * 1024 + i];
    if (tid < 64) { slng[tid] = lng_g[tid]; slnb[tid] = lnb_g[tid]; }

    const float4* gbase = reinterpret_cast<const float4*>(
        inputs + ((size_t)b * NKV + n0) * D);
    uint32_t sxa[2];
    sxa[0] = (uint32_t)__cvta_generic_to_shared(sxf0);
    sxa[1] = (uint32_t)__cvta_generic_to_shared(sxf1);
    const uint32_t sat_s = (uint32_t)__cvta_generic_to_shared(satb);
    const uint32_t sxb_s = (uint32_t)__cvta_generic_to_shared(sxb);

    // ldmatrix base addresses (loop-invariant)
    const int mblk = w & 1;
    const int ncol = (w >> 1) * 32;
    const int l = lane;
    const uint32_t aAddr = sat_s +
        (uint32_t)((16 * mblk + (l & 7) + ((l >> 3) & 1) * 8) * (SATB * 2) + (l >> 4) * 16);
    const uint32_t bAddr = sxb_s +
        (uint32_t)((l & 15) * (SXBU * 4) + (ncol + ((l >> 4) & 1) * 8) * 2);

    // prefetch tile 0 (64 tokens x 64 f32 = 1024 float4)
    #pragma unroll
    for (int k = 0; k < 8; k++) {
        int i = tid + 128 * k;
        cp_async16(sxa[0] + ((i >> 4) * SXF + (i & 15) * 4) * 4, gbase + i);
    }
    cp_commit();

    float c2[4][4];        // GEMM2 accumulators (persist across tiles)
    float colsum[4][2];
    #pragma unroll
    for (int a = 0; a < 4; a++) {
        #pragma unroll
        for (int i = 0; i < 4; i++) c2[a][i] = 0.f;
        colsum[a][0] = 0.f; colsum[a][1] = 0.f;
    }

    #pragma unroll
    for (int t4 = 0; t4 < NTILES; t4++) {
        const float* sxf = (t4 & 1) ? sxf1 : sxf0;

        cp_wait0();
        __syncthreads();

        if (t4 + 1 < NTILES) {
            const float4* gn = gbase + (size_t)(t4 + 1) * (TT * D / 4);
            uint32_t dst = sxa[(t4 + 1) & 1];
            #pragma unroll
            for (int k = 0; k < 8; k++) {
                int i = tid + 128 * k;
                cp_async16(dst + ((i >> 4) * SXF + (i & 15) * 4) * 4, gn + i);
            }
            cp_commit();
        }

        // ---- layernorm: rows r0, r0+8; cols (2t+8m, 2t+8m+1), m=0..7 ----
        float2 x0[8], x1[8];
        float s0 = 0.f, q0 = 0.f, s1 = 0.f, q1 = 0.f;
        {
            const float* p0 = sxf + r0 * SXF + 2 * t;
            const float* p1 = p0 + 8 * SXF;
            #pragma unroll
            for (int m = 0; m < 8; m++) {
                x0[m] = *reinterpret_cast<const float2*>(p0 + 8 * m);
                x1[m] = *reinterpret_cast<const float2*>(p1 + 8 * m);
                s0 += x0[m].x + x0[m].y;
                q0 = fmaf(x0[m].x, x0[m].x, fmaf(x0[m].y, x0[m].y, q0));
                s1 += x1[m].x + x1[m].y;
                q1 = fmaf(x1[m].x, x1[m].x, fmaf(x1[m].y, x1[m].y, q1));
            }
        }
        s0 += __shfl_xor_sync(0xffffffffu, s0, 1);
        q0 += __shfl_xor_sync(0xffffffffu, q0, 1);
        s1 += __shfl_xor_sync(0xffffffffu, s1, 1);
        q1 += __shfl_xor_sync(0xffffffffu, q1, 1);
        s0 += __shfl_xor_sync(0xffffffffu, s0, 2);
        q0 += __shfl_xor_sync(0xffffffffu, q0, 2);
        s1 += __shfl_xor_sync(0xffffffffu, s1, 2);
        q1 += __shfl_xor_sync(0xffffffffu, q1, 2);
        float mu0 = s0 * (1.f / 64.f), mu1 = s1 * (1.f / 64.f);
        float rs0 = rsqrtf(fmaf(-mu0, mu0, q0 * (1.f / 64.f)) + 1e-5f);
        float rs1 = rsqrtf(fmaf(-mu1, mu1, q1 * (1.f / 64.f)) + 1e-5f);

        uint32_t v0p[8], v1p[8];
        {
            uint32_t* o0 = sxb + r0 * SXBU + t;
            uint32_t* o1 = o0 + 8 * SXBU;
            #pragma unroll
            for (int m = 0; m < 8; m++) {
                float2 gb = *reinterpret_cast<const float2*>(slng + 2 * t + 8 * m);
                float2 bb = *reinterpret_cast<const float2*>(slnb + 2 * t + 8 * m);
                float y00 = fmaf((x0[m].x - mu0) * rs0, gb.x, bb.x);
                float y01 = fmaf((x0[m].y - mu0) * rs0, gb.y, bb.y);
                float y10 = fmaf((x1[m].x - mu1) * rs1, gb.x, bb.x);
                float y11 = fmaf((x1[m].y - mu1) * rs1, gb.y, bb.y);
                v0p[m] = pack_bf16x2(y00, y01);
                v1p[m] = pack_bf16x2(y10, y11);
                o0[4 * m] = v0p[m];
                o1[4 * m] = v1p[m];
            }
        }

        // ---- GEMM1: logits[64,32] = lnX @ Wfold (A from regs) ----
        float c1[4][4];
        #pragma unroll
        for (int j = 0; j < 4; j++)
            #pragma unroll
            for (int i = 0; i < 4; i++) c1[j][i] = 0.f;
        #pragma unroll
        for (int ks = 0; ks < 4; ks++) {
            uint32_t a0 = v0p[2 * ks],     a1 = v1p[2 * ks];
            uint32_t a2 = v0p[2 * ks + 1], a3 = v1p[2 * ks + 1];
            #pragma unroll
            for (int j = 0; j < 4; j++) {
                uint32_t b0 = wfT[(8 * j + g) * WFU + 8 * ks + t];
                uint32_t b1 = wfT[(8 * j + g) * WFU + 8 * ks + t + 4];
                mma16(c1[j], a0, a1, a2, a3, b0, b1);
            }
        }

        // ---- softmax over 32 cols for rows r0, r0+8 ----
        float m0 = -1e30f, m1 = -1e30f;
        #pragma unroll
        for (int j = 0; j < 4; j++) {
            m0 = fmaxf(m0, fmaxf(c1[j][0], c1[j][1]));
            m1 = fmaxf(m1, fmaxf(c1[j][2], c1[j][3]));
        }
        m0 = fmaxf(m0, __shfl_xor_sync(0xffffffffu, m0, 1));
        m0 = fmaxf(m0, __shfl_xor_sync(0xffffffffu, m0, 2));
        m1 = fmaxf(m1, __shfl_xor_sync(0xffffffffu, m1, 1));
        m1 = fmaxf(m1, __shfl_xor_sync(0xffffffffu, m1, 2));
        float ss0 = 0.f, ss1 = 0.f;
        #pragma unroll
        for (int j = 0; j < 4; j++) {
            c1[j][0] = __expf(c1[j][0] - m0);
            c1[j][1] = __expf(c1[j][1] - m0);
            c1[j][2] = __expf(c1[j][2] - m1);
            c1[j][3] = __expf(c1[j][3] - m1);
            ss0 += c1[j][0] + c1[j][1];
            ss1 += c1[j][2] + c1[j][3];
        }
        ss0 += __shfl_xor_sync(0xffffffffu, ss0, 1);
        ss0 += __shfl_xor_sync(0xffffffffu, ss0, 2);
        ss1 += __shfl_xor_sync(0xffffffffu, ss1, 1);
        ss1 += __shfl_xor_sync(0xffffffffu, ss1, 2);
        float inv0 = 1.f / ss0, inv1 = 1.f / ss1;

        if (last) {
            float w00 = 0.f, w01 = 0.f, w10 = 0.f, w11 = 0.f;
            #pragma unroll
            for (int j = 0; j < 4; j++) {
                w00 += c1[j][0]; w01 += c1[j][1];
                w10 += c1[j][2]; w11 += c1[j][3];
            }
            size_t nrow = (size_t)b * NKV + n0 + t4 * TT;
            *reinterpret_cast<float2*>(&vis[(nrow + r0) * NQ + 2 * t])
                = make_float2(w00 * inv0, w01 * inv0);
            *reinterpret_cast<float2*>(&vis[(nrow + r0 + 8) * NQ + 2 * t])
                = make_float2(w10 * inv1, w11 * inv1);
        }

        // ---- attn+eps -> satb (bf16, transposed) + column sums ----
        #pragma unroll
        for (int j = 0; j < 4; j++) {
            int cc = 8 * j + 2 * t;
            float a00 = fmaf(c1[j][0], inv0, EPS_A);
            float a01 = fmaf(c1[j][1], inv0, EPS_A);
            float a10 = fmaf(c1[j][2], inv1, EPS_A);
            float a11 = fmaf(c1[j][3], inv1, EPS_A);
            satb[cc * SATB + r0]           = __float2bfloat16(a00);
            satb[(cc + 1) * SATB + r0]     = __float2bfloat16(a01);
            satb[cc * SATB + r0 + 8]       = __float2bfloat16(a10);
            satb[(cc + 1) * SATB + r0 + 8] = __float2bfloat16(a11);
            colsum[j][0] += a00 + a10;
            colsum[j][1] += a01 + a11;
        }
        __syncthreads();

        // ---- GEMM2: S'[32,64] += attn^T[32,64] @ lnX[64,64] (ldmatrix) ----
        #pragma unroll
        for (int ks = 0; ks < 4; ks++) {
            uint32_t a0, a1, a2, a3, f0, f1, f2, f3;
            ldm_x4(a0, a1, a2, a3, aAddr + ks * 32);
            ldm_x4t(f0, f1, f2, f3, bAddr + ks * (16 * SXBU * 4));
            mma16(c2[0], a0, a1, a2, a3, f0, f1);
            mma16(c2[1], a0, a1, a2, a3, f2, f3);
            ldm_x4t(f0, f1, f2, f3, bAddr + ks * (16 * SXBU * 4) + 32);
            mma16(c2[2], a0, a1, a2, a3, f0, f1);
            mma16(c2[3], a0, a1, a2, a3, f2, f3);
        }
    }

    // ---- epilogue: per-chunk partials ----
    {
        const int crow = 16 * mblk + g;
        float* pp = &g_part[(size_t)(b * NCHUNK + chunk) * (C32 * D)];
        #pragma unroll
        for (int nb = 0; nb < 4; nb++) {
            int e0 = ncol + 8 * nb + 2 * t;
            pp[crow * D + e0]           = c2[nb][0];
            pp[crow * D + e0 + 1]       = c2[nb][1];
            pp[(crow + 8) * D + e0]     = c2[nb][2];
            pp[(crow + 8) * D + e0 + 1] = c2[nb][3];
        }
        #pragma unroll
        for (int off = 4; off < 32; off <<= 1) {
            #pragma unroll
            for (int j = 0; j < 4; j++) {
                colsum[j][0] += __shfl_xor_sync(0xffffffffu, colsum[j][0], off);
                colsum[j][1] += __shfl_xor_sync(0xffffffffu, colsum[j][1], off);
            }
        }
        __syncthreads();
        float* scs = (float*)satb;   // dead region reused: [4 warps][32]
        if (g == 0) {
            #pragma unroll
            for (int j = 0; j < 4; j++) {
                scs[w * 32 + 8 * j + 2 * t]     = colsum[j][0];
                scs[w * 32 + 8 * j + 2 * t + 1] = colsum[j][1];
            }
        }
        __syncthreads();
        if (tid < C32) {
            float s = 0.f;
            #pragma unroll
            for (int ww = 0; ww < 4; ww++) s += scs[ww * 32 + tid];
            g_sap[(b * NCHUNK + chunk) * C32 + tid] = s;
        }
    }

    // ---- arrival counter; last CTA of this batch runs the slot update ----
    __threadfence();
    __syncthreads();
    if (tid == 0) {
        int old = atomicAdd(&g_cnt[b], 1);
        ((volatile int*)sm)[0] = (old == NCHUNK - 1) ? 1 : 0;
    }
    __syncthreads();
    const int do_tail = ((volatile int*)sm)[0];
    __syncthreads();
    if (!do_tail) return;
    if (tid == 0) g_cnt[b] = 0;      // self-reset for next launch
    __threadfence();                 // acquire partials

    // -------- slot-update tail (128 threads, whole batch b) --------
    float* T      = sm;
    float* t_sax  = T;               // [32][68]
    float* t_sa   = T + 2176;        // [32]
    float* t_sl   = T + 2208;        // [8][64] prev slots / final slots
    float* t_up   = T + 2720;        // [8][64] updates -> new slots
    float* t_gx   = T + 3232;        // [8][192]
    float* t_gh   = T + 4768;        // [8][192]
    float* t_ln   = T + 6304;        // [8][64]
    float* t_hid  = T + 6816;        // [8][128]

    // A: reduce partials (fixed chunk order -> deterministic)
    for (int i = tid; i < 512; i += 128) {
        const float4* gp = reinterpret_cast<const float4*>(
            g_part + (size_t)b * NCHUNK * (C32 * D)) + i;
        float4 acc = make_float4(0.f, 0.f, 0.f, 0.f);
        #pragma unroll
        for (int ch = 0; ch < NCHUNK; ch++) {
            float4 v = gp[ch * 512];
            acc.x += v.x; acc.y += v.y; acc.z += v.z; acc.w += v.w;
        }
        int c = i >> 4, e0 = (i & 15) * 4;
        *reinterpret_cast<float4*>(&t_sax[c * SXF + e0]) = acc;
    }
    if (tid < C32) {
        float acc = 0.f;
        #pragma unroll
        for (int ch = 0; ch < NCHUNK; ch++)
            acc += g_sap[(b * NCHUNK + ch) * C32 + tid];
        t_sa[tid] = acc;
    }
    for (int i = tid; i < 512; i += 128) t_sl[i] = g_slots[b * 512 + i];
    __syncthreads();

    // B: updates = (S' @ Wv) / sa
    for (int o = tid; o < 512; o += 128) {
        int q = o >> 6, hd = o & 63, h = hd >> 4, c = h * 8 + q;
        const float* sr = t_sax + c * SXF;
        float acc = 0.f;
        #pragma unroll
        for (int e = 0; e < 64; e++)
            acc = fmaf(sr[e], Wv[e * 64 + hd], acc);
        t_up[o] = acc / t_sa[c];
    }
    __syncthreads();

    // C: GRU gates
    for (int o = tid; o < 1536; o += 128) {
        int q = o / 192, cc = o - q * 192;
        const float4* wi = reinterpret_cast<const float4*>(W_ih + cc * 64);
        const float4* wh = reinterpret_cast<const float4*>(W_hh + cc * 64);
        const float4* xu = reinterpret_cast<const float4*>(t_up + q * 64);
        const float4* xs = reinterpret_cast<const float4*>(t_sl + q * 64);
        float gx = b_ih[cc], gh = b_hh[cc];
        #pragma unroll
        for (int d4 = 0; d4 < 16; d4++) {
            float4 a = xu[d4], wa = wi[d4];
            float4 bb = xs[d4], wb = wh[d4];
            gx = fmaf(a.x, wa.x, fmaf(a.y, wa.y, fmaf(a.z, wa.z, fmaf(a.w, wa.w, gx))));
            gh = fmaf(bb.x, wb.x, fmaf(bb.y, wb.y, fmaf(bb.z, wb.z, fmaf(bb.w, wb.w, gh))));
        }
        t_gx[q * 192 + cc] = gx;
        t_gh[q * 192 + cc] = gh;
    }
    __syncthreads();

    // D: GRU combine -> new slots in t_up
    for (int o = tid; o < 512; o += 128) {
        int q = o >> 6, dd = o & 63;
        float r = sigm(t_gx[q * 192 + dd]       + t_gh[q * 192 + dd]);
        float z = sigm(t_gx[q * 192 + 64 + dd]  + t_gh[q * 192 + 64 + dd]);
        float n = tanhf(t_gx[q * 192 + 128 + dd] + r * t_gh[q * 192 + 128 + dd]);
        t_up[o] = (1.f - z) * n + z * t_sl[o];
    }
    __syncthreads();

    // E: MLP layernorm
    #pragma unroll
    for (int rep = 0; rep < 2; rep++) {
        int q = w + 4 * rep;
        float x0 = t_up[q * 64 + lane], x1 = t_up[q * 64 + 32 + lane];
        float s = x0 + x1, qq = x0 * x0 + x1 * x1;
        #pragma unroll
        for (int off = 16; off; off >>= 1) {
            s  += __shfl_xor_sync(0xffffffffu, s,  off);
            qq += __shfl_xor_sync(0xffffffffu, qq, off);
        }
        float m = s * (1.f / 64.f);
        float rs = rsqrtf(qq * (1.f / 64.f) - m * m + 1e-5f);
        t_ln[q * 64 + lane]      = (x0 - m) * rs * lnm_g[lane]      + lnm_b[lane];
        t_ln[q * 64 + 32 + lane] = (x1 - m) * rs * lnm_g[lane + 32] + lnm_b[lane + 32];
    }
    __syncthreads();

    // F: hidden = relu(ln @ W1 + b1)
    for (int o = tid; o < 1024; o += 128) {
        int q = o >> 7, j = o & 127;
        float acc = b1v[j];
        #pragma unroll
        for (int dd = 0; dd < 64; dd++)
            acc = fmaf(t_ln[q * 64 + dd], W1[dd * 128 + j], acc);
        t_hid[o] = fmaxf(acc, 0.f);
    }
    __syncthreads();

    // G: final slots = new + hid @ W2 + b2
    for (int o = tid; o < 512; o += 128) {
        int q = o >> 6, dd = o & 63;
        float acc = b2v[dd];
        #pragma unroll
        for (int j = 0; j < 128; j++)
            acc = fmaf(t_hid[q * 128 + j], W2[j * 64 + dd], acc);
        float fin = t_up[o] + acc;
        t_sl[o] = fin;
        g_slots[b * 512 + o] = fin;
        if (last) out_slots[b * 512 + o] = fin;
    }
    __syncthreads();
    if (last) return;

    // H: slot layernorm
    #pragma unroll
    for (int rep = 0; rep < 2; rep++) {
        int q = w + 4 * rep;
        float x0 = t_sl[q * 64 + lane], x1 = t_sl[q * 64 + 32 + lane];
        float s = x0 + x1, qq = x0 * x0 + x1 * x1;
        #pragma unroll
        for (int off = 16; off; off >>= 1) {
            s  += __shfl_xor_sync(0xffffffffu, s,  off);
            qq += __shfl_xor_sync(0xffffffffu, qq, off);
        }
        float m = s * (1.f / 64.f);
        float rs = rsqrtf(qq * (1.f / 64.f) - m * m + 1e-5f);
        t_ln[q * 64 + lane]      = (x0 - m) * rs * lns_g[lane]      + lns_b[lane];
        t_ln[q * 64 + 32 + lane] = (x1 - m) * rs * lns_g[lane + 32] + lns_b[lane + 32];
    }
    __syncthreads();

    // I: qm = ln(slots) @ Wq  (into t_hid)
    for (int o = tid; o < 512; o += 128) {
        int q = o >> 6, e = o & 63;
        float acc = 0.f;
        #pragma unroll
        for (int dd = 0; dd < 64; dd++)
            acc = fmaf(t_ln[q * 64 + dd], Wq[dd * 64 + e], acc);
        t_hid[o] = acc;
    }
    __syncthreads();

    // J: Wfold (bf16x2 packed): Wfold[c][e] = 0.25 * sum_d Wk[e,h16+d]*qm[q,h16+d]
    for (int o = tid; o < 1024; o += 128) {
        int c = o >> 5, ep = o & 31, h = c >> 3, q = c & 7;
        float a0 = 0.f, a1 = 0.f;
        #pragma unroll
        for (int dd = 0; dd < 16; dd++) {
            float qv = t_hid[q * 64 + h * 16 + dd];
            a0 = fmaf(Wk[(2 * ep) * 64 + h * 16 + dd],     qv, a0);
            a1 = fmaf(Wk[(2 * ep + 1) * 64 + h * 16 + dd], qv, a1);
        }
        g_wfoldu[b * 1024 + c * 32 + ep] = pack_bf16x2(0.25f * a0, 0.25f * a1);
    }
}

// =====================================================================
// Init kernel: slots -> g_slots; slot LN -> qm -> Wfold0
// =====================================================================
__global__ void __launch_bounds__(128)
vslot_init(const float* __restrict__ slots_in,
           const float* __restrict__ Wq, const float* __restrict__ Wk,
           const float* __restrict__ lns_g, const float* __restrict__ lns_b)
{
    __shared__ float s_s[512], s_ln[512], s_qm[512];
    const int b = blockIdx.x, tid = threadIdx.x;
    const int w = tid >> 5, lane = tid & 31;

    for (int i = tid; i < 512; i += 128) {
        float v = slots_in[b * 512 + i];
        s_s[i] = v;
        g_slots[b * 512 + i] = v;
    }
    __syncthreads();

    #pragma unroll
    for (int rep = 0; rep < 2; rep++) {
        int q = w + 4 * rep;
        float x0 = s_s[q * 64 + lane], x1 = s_s[q * 64 + 32 + lane];
        float s = x0 + x1, qq = x0 * x0 + x1 * x1;
        #pragma unroll
        for (int off = 16; off; off >>= 1) {
            s  += __shfl_xor_sync(0xffffffffu, s,  off);
            qq += __shfl_xor_sync(0xffffffffu, qq, off);
        }
        float m = s * (1.f / 64.f);
        float rs = rsqrtf(qq * (1.f / 64.f) - m * m + 1e-5f);
        s_ln[q * 64 + lane]      = (x0 - m) * rs * lns_g[lane]      + lns_b[lane];
        s_ln[q * 64 + 32 + lane] = (x1 - m) * rs * lns_g[lane + 32] + lns_b[lane + 32];
    }
    __syncthreads();

    for (int o = tid; o < 512; o += 128) {
        int q = o >> 6, e = o & 63;
        float acc = 0.f;
        #pragma unroll
        for (int dd = 0; dd < 64; dd++)
            acc = fmaf(s_ln[q * 64 + dd], Wq[dd * 64 + e], acc);
        s_qm[o] = acc;
    }
    __syncthreads();

    for (int o = tid; o < 1024; o += 128) {
        int c = o >> 5, ep = o & 31, h = c >> 3, q = c & 7;
        float a0 = 0.f, a1 = 0.f;
        #pragma unroll
        for (int dd = 0; dd < 16; dd++) {
            float qv = s_qm[q * 64 + h * 16 + dd];
            a0 = fmaf(Wk[(2 * ep) * 64 + h * 16 + dd],     qv, a0);
            a1 = fmaf(Wk[(2 * ep + 1) * 64 + h * 16 + dd], qv, a1);
        }
        g_wfoldu[b * 1024 + c * 32 + ep] = pack_bf16x2(0.25f * a0, 0.25f * a1);
    }
}

// =====================================================================
// launcher
// =====================================================================
extern "C" void kernel_launch(void* const* d_in, const int* in_sizes, int n_in,
                              void* d_out, int out_size)
{
    const float* inputs = (const float*)d_in[0];
    const float* slots  = (const float*)d_in[1];
    const float* lnin_g = (const float*)d_in[2];
    const float* lnin_b = (const float*)d_in[3];
    const float* lns_g  = (const float*)d_in[4];
    const float* lns_b  = (const float*)d_in[5];
    const float* lnm_g  = (const float*)d_in[6];
    const float* lnm_b  = (const float*)d_in[7];
    const float* Wq     = (const float*)d_in[8];
    const float* Wk     = (const float*)d_in[9];
    const float* Wv     = (const float*)d_in[10];
    const float* W_ih   = (const float*)d_in[11];
    const float* W_hh   = (const float*)d_in[12];
    const float* b_ih   = (const float*)d_in[13];
    const float* b_hh   = (const float*)d_in[14];
    const float* W1     = (const float*)d_in[15];
    const float* b1     = (const float*)d_in[16];
    const float* W2     = (const float*)d_in[17];
    const float* b2     = (const float*)d_in[18];

    float* out       = (float*)d_out;
    float* out_slots = out;                  // [64, 8, 64]
    float* out_vis   = out + B_ * NQ * D;    // [64, 8192, 8]

    // dynamic smem: 2*64*68*4 + 64*36*4 + 32*72*2 + 32*36*4 + 128*4 = 53760 B
    size_t smem = 2 * TT * SXF * 4 + TT * SXBU * 4 + C32 * SATB * 2
                + C32 * WFU * 4 + 128 * 4;
    cudaFuncSetAttribute(vslot_main,
                         cudaFuncAttributeMaxDynamicSharedMemorySize, (int)smem);

#define MAIN_K(lastf)                                                          \
    vslot_main<<<B_ * NCHUNK, 128, smem>>>(inputs, lnin_g, lnin_b, out_vis,    \
        (lastf), Wq, Wk, Wv, W_ih, W_hh, b_ih, b_hh, lns_g, lns_b,             \
        lnm_g, lnm_b, W1, b1, W2, b2, out_slots)

    vslot_init<<<B_, 128>>>(slots, Wq, Wk, lns_g, lns_b);
    MAIN_K(0);   // iter 0 + slot update 0 (in-kernel tail)
    MAIN_K(0);   // iter 1 + slot update 1
    MAIN_K(1);   // iter 2 + final slot update -> out_slots, vis written
#undef MAIN_K
}

// round 7
// speedup vs baseline: 2.5724x; 2.5724x over previous
#include <cuda_runtime.h>
#include <cuda_bf16.h>
#include <cstdint>
#include <cstddef>

// ---------------- problem constants ----------------
#define B_     64
#define NKV    8192
#define D      64      // INPUT_SIZE == SLOT_SIZE
#define NQ     8
#define C32    32      // NUM_HEADS * NUM_SLOTS
#define EPS_A  1e-8f
#define NCHUNK 32
#define TPC    256     // tokens per CTA
#define TT     64      // tokens per tile
#define NTILES (TPC / TT)   // 4

// smem strides
#define SXF 68         // fp32 input tile row stride (floats)
#define SXBU 36        // bf16 lnX tile row stride (u32 = bf16x2)
#define SATB 72        // attn^T row stride (bf16)
#define WFU 36         // WfoldT row stride (u32)

// ---------------- device scratch (no allocs allowed) ----------------
__device__ uint32_t g_wfoldu[B_ * C32 * 32];         // [b][c][e/2] bf16x2
__device__ float    g_part [B_ * NCHUNK * C32 * D];  // per-chunk S' partials
__device__ float    g_sap  [B_ * NCHUNK * C32];      // per-chunk colsum partials
__device__ float    g_slots[B_ * NQ * D];            // working slots

// ---------------- helpers ----------------
__device__ __forceinline__ uint32_t pack_bf16x2(float lo, float hi) {
    uint32_t r;
    asm("cvt.rn.bf16x2.f32 %0, %1, %2;" : "=r"(r) : "f"(hi), "f"(lo));
    return r;
}

__device__ __forceinline__ void mma16(float c[4],
                                      uint32_t a0, uint32_t a1, uint32_t a2, uint32_t a3,
                                      uint32_t b0, uint32_t b1) {
    asm volatile(
        "mma.sync.aligned.m16n8k16.row.col.f32.bf16.bf16.f32 "
        "{%0,%1,%2,%3},{%4,%5,%6,%7},{%8,%9},{%0,%1,%2,%3};"
        : "+f"(c[0]), "+f"(c[1]), "+f"(c[2]), "+f"(c[3])
        : "r"(a0), "r"(a1), "r"(a2), "r"(a3), "r"(b0), "r"(b1));
}

__device__ __forceinline__ void ldm_x4(uint32_t& r0, uint32_t& r1, uint32_t& r2, uint32_t& r3,
                                       uint32_t addr) {
    asm volatile("ldmatrix.sync.aligned.m8n8.x4.shared.b16 {%0,%1,%2,%3}, [%4];"
                 : "=r"(r0), "=r"(r1), "=r"(r2), "=r"(r3) : "r"(addr));
}
__device__ __forceinline__ void ldm_x4t(uint32_t& r0, uint32_t& r1, uint32_t& r2, uint32_t& r3,
                                        uint32_t addr) {
    asm volatile("ldmatrix.sync.aligned.m8n8.x4.trans.shared.b16 {%0,%1,%2,%3}, [%4];"
                 : "=r"(r0), "=r"(r1), "=r"(r2), "=r"(r3) : "r"(addr));
}

__device__ __forceinline__ void cp_async16(uint32_t smem_addr, const void* gptr) {
    asm volatile("cp.async.cg.shared.global [%0], [%1], 16;"
                 :: "r"(smem_addr), "l"(gptr));
}
__device__ __forceinline__ void cp_commit() { asm volatile("cp.async.commit_group;"); }
__device__ __forceinline__ void cp_wait0()  { asm volatile("cp.async.wait_group 0;"); }

// =====================================================================
// Main fused streaming kernel (LEAN — no slot tail): one CTA per
// (batch, 256-token chunk), 128 threads, 4 CTAs/SM, bf16 m16n8k16.
// =====================================================================
__global__ void __launch_bounds__(128, 4)
vslot_main(const float* __restrict__ inputs,
           const float* __restrict__ lng_g,
           const float* __restrict__ lnb_g,
           float* __restrict__ vis,
           int last)
{
    extern __shared__ float sm[];
    float*          sxf0 = sm;                                   // [64][68] f32
    float*          sxf1 = sxf0 + TT * SXF;                      // [64][68] f32
    uint32_t*       sxb  = (uint32_t*)(sxf1 + TT * SXF);         // [64][36] u32 (bf16x2 lnX)
    __nv_bfloat16*  satb = (__nv_bfloat16*)(sxb + TT * SXBU);    // [32][72] bf16 attn^T
    uint32_t*       wfT  = (uint32_t*)(satb + C32 * SATB);       // [32][36] u32 WfoldT
    float*          slng = (float*)(wfT + C32 * WFU);            // [64]
    float*          slnb = slng + 64;                            // [64]

    const int b     = blockIdx.x >> 5;
    const int chunk = blockIdx.x & 31;
    const int n0    = chunk * TPC;
    const int tid   = threadIdx.x;
    const int w     = tid >> 5;       // 0..3
    const int lane  = tid & 31;
    const int g     = lane >> 2;      // 0..7
    const int t     = lane & 3;       // 0..3
    const int r0    = w * 16 + g;     // mma rows r0, r0+8 (tokens in tile)

    // prologue loads
    for (int i = tid; i < C32 * 32; i += 128)
        wfT[(i >> 5) * WFU + (i & 31)] = g_wfoldu[b * 1024 + i];
    if (tid < 64) { slng[tid] = lng_g[tid]; slnb[tid] = lnb_g[tid]; }

    const float4* gbase = reinterpret_cast<const float4*>(
        inputs + ((size_t)b * NKV + n0) * D);
    uint32_t sxa[2];
    sxa[0] = (uint32_t)__cvta_generic_to_shared(sxf0);
    sxa[1] = (uint32_t)__cvta_generic_to_shared(sxf1);
    const uint32_t sat_s = (uint32_t)__cvta_generic_to_shared(satb);
    const uint32_t sxb_s = (uint32_t)__cvta_generic_to_shared(sxb);

    // ldmatrix base addresses (loop-invariant, bank-conflict-free)
    const int mblk = w & 1;
    const int ncol = (w >> 1) * 32;
    const int l = lane;
    const uint32_t aAddr = sat_s +
        (uint32_t)((16 * mblk + (l & 7) + ((l >> 3) & 1) * 8) * (SATB * 2) + (l >> 4) * 16);
    const uint32_t bAddr = sxb_s +
        (uint32_t)((l & 15) * (SXBU * 4) + (ncol + ((l >> 4) & 1) * 8) * 2);

    // prefetch tile 0 (64 tokens x 64 f32 = 1024 float4)
    #pragma unroll
    for (int k = 0; k < 8; k++) {
        int i = tid + 128 * k;
        cp_async16(sxa[0] + ((i >> 4) * SXF + (i & 15) * 4) * 4, gbase + i);
    }
    cp_commit();

    float c2[4][4];        // GEMM2 accumulators (persist across tiles)
    float colsum[4][2];
    #pragma unroll
    for (int a = 0; a < 4; a++) {
        #pragma unroll
        for (int i = 0; i < 4; i++) c2[a][i] = 0.f;
        colsum[a][0] = 0.f; colsum[a][1] = 0.f;
    }

    #pragma unroll
    for (int t4 = 0; t4 < NTILES; t4++) {
        const float* sxf = (t4 & 1) ? sxf1 : sxf0;

        cp_wait0();
        __syncthreads();

        if (t4 + 1 < NTILES) {
            const float4* gn = gbase + (size_t)(t4 + 1) * (TT * D / 4);
            uint32_t dst = sxa[(t4 + 1) & 1];
            #pragma unroll
            for (int k = 0; k < 8; k++) {
                int i = tid + 128 * k;
                cp_async16(dst + ((i >> 4) * SXF + (i & 15) * 4) * 4, gn + i);
            }
            cp_commit();
        }

        // ---- layernorm: rows r0, r0+8; cols (2t+8m, 2t+8m+1), m=0..7 ----
        float2 x0[8], x1[8];
        float s0 = 0.f, q0 = 0.f, s1 = 0.f, q1 = 0.f;
        {
            const float* p0 = sxf + r0 * SXF + 2 * t;
            const float* p1 = p0 + 8 * SXF;
            #pragma unroll
            for (int m = 0; m < 8; m++) {
                x0[m] = *reinterpret_cast<const float2*>(p0 + 8 * m);
                x1[m] = *reinterpret_cast<const float2*>(p1 + 8 * m);
                s0 += x0[m].x + x0[m].y;
                q0 = fmaf(x0[m].x, x0[m].x, fmaf(x0[m].y, x0[m].y, q0));
                s1 += x1[m].x + x1[m].y;
                q1 = fmaf(x1[m].x, x1[m].x, fmaf(x1[m].y, x1[m].y, q1));
            }
        }
        s0 += __shfl_xor_sync(0xffffffffu, s0, 1);
        q0 += __shfl_xor_sync(0xffffffffu, q0, 1);
        s1 += __shfl_xor_sync(0xffffffffu, s1, 1);
        q1 += __shfl_xor_sync(0xffffffffu, q1, 1);
        s0 += __shfl_xor_sync(0xffffffffu, s0, 2);
        q0 += __shfl_xor_sync(0xffffffffu, q0, 2);
        s1 += __shfl_xor_sync(0xffffffffu, s1, 2);
        q1 += __shfl_xor_sync(0xffffffffu, q1, 2);
        float mu0 = s0 * (1.f / 64.f), mu1 = s1 * (1.f / 64.f);
        float rs0 = rsqrtf(fmaf(-mu0, mu0, q0 * (1.f / 64.f)) + 1e-5f);
        float rs1 = rsqrtf(fmaf(-mu1, mu1, q1 * (1.f / 64.f)) + 1e-5f);

        uint32_t v0p[8], v1p[8];
        {
            uint32_t* o0 = sxb + r0 * SXBU + t;
            uint32_t* o1 = o0 + 8 * SXBU;
            #pragma unroll
            for (int m = 0; m < 8; m++) {
                float2 gb = *reinterpret_cast<const float2*>(slng + 2 * t + 8 * m);
                float2 bb = *reinterpret_cast<const float2*>(slnb + 2 * t + 8 * m);
                float y00 = fmaf((x0[m].x - mu0) * rs0, gb.x, bb.x);
                float y01 = fmaf((x0[m].y - mu0) * rs0, gb.y, bb.y);
                float y10 = fmaf((x1[m].x - mu1) * rs1, gb.x, bb.x);
                float y11 = fmaf((x1[m].y - mu1) * rs1, gb.y, bb.y);
                v0p[m] = pack_bf16x2(y00, y01);
                v1p[m] = pack_bf16x2(y10, y11);
                o0[4 * m] = v0p[m];
                o1[4 * m] = v1p[m];
            }
        }

        // ---- GEMM1: logits[64,32] = lnX @ Wfold (A from regs) ----
        float c1[4][4];
        #pragma unroll
        for (int j = 0; j < 4; j++)
            #pragma unroll
            for (int i = 0; i < 4; i++) c1[j][i] = 0.f;
        #pragma unroll
        for (int ks = 0; ks < 4; ks++) {
            uint32_t a0 = v0p[2 * ks],     a1 = v1p[2 * ks];
            uint32_t a2 = v0p[2 * ks + 1], a3 = v1p[2 * ks + 1];
            #pragma unroll
            for (int j = 0; j < 4; j++) {
                uint32_t b0 = wfT[(8 * j + g) * WFU + 8 * ks + t];
                uint32_t b1 = wfT[(8 * j + g) * WFU + 8 * ks + t + 4];
                mma16(c1[j], a0, a1, a2, a3, b0, b1);
            }
        }

        // ---- softmax over 32 cols for rows r0, r0+8 ----
        float m0 = -1e30f, m1 = -1e30f;
        #pragma unroll
        for (int j = 0; j < 4; j++) {
            m0 = fmaxf(m0, fmaxf(c1[j][0], c1[j][1]));
            m1 = fmaxf(m1, fmaxf(c1[j][2], c1[j][3]));
        }
        m0 = fmaxf(m0, __shfl_xor_sync(0xffffffffu, m0, 1));
        m0 = fmaxf(m0, __shfl_xor_sync(0xffffffffu, m0, 2));
        m1 = fmaxf(m1, __shfl_xor_sync(0xffffffffu, m1, 1));
        m1 = fmaxf(m1, __shfl_xor_sync(0xffffffffu, m1, 2));
        float ss0 = 0.f, ss1 = 0.f;
        #pragma unroll
        for (int j = 0; j < 4; j++) {
            c1[j][0] = __expf(c1[j][0] - m0);
            c1[j][1] = __expf(c1[j][1] - m0);
            c1[j][2] = __expf(c1[j][2] - m1);
            c1[j][3] = __expf(c1[j][3] - m1);
            ss0 += c1[j][0] + c1[j][1];
            ss1 += c1[j][2] + c1[j][3];
        }
        ss0 += __shfl_xor_sync(0xffffffffu, ss0, 1);
        ss0 += __shfl_xor_sync(0xffffffffu, ss0, 2);
        ss1 += __shfl_xor_sync(0xffffffffu, ss1, 1);
        ss1 += __shfl_xor_sync(0xffffffffu, ss1, 2);
        float inv0 = 1.f / ss0, inv1 = 1.f / ss1;

        if (last) {
            float w00 = 0.f, w01 = 0.f, w10 = 0.f, w11 = 0.f;
            #pragma unroll
            for (int j = 0; j < 4; j++) {
                w00 += c1[j][0]; w01 += c1[j][1];
                w10 += c1[j][2]; w11 += c1[j][3];
            }
            size_t nrow = (size_t)b * NKV + n0 + t4 * TT;
            *reinterpret_cast<float2*>(&vis[(nrow + r0) * NQ + 2 * t])
                = make_float2(w00 * inv0, w01 * inv0);
            *reinterpret_cast<float2*>(&vis[(nrow + r0 + 8) * NQ + 2 * t])
                = make_float2(w10 * inv1, w11 * inv1);
        }

        // ---- attn+eps -> satb (bf16, transposed) + column sums ----
        #pragma unroll
        for (int j = 0; j < 4; j++) {
            int cc = 8 * j + 2 * t;
            float a00 = fmaf(c1[j][0], inv0, EPS_A);
            float a01 = fmaf(c1[j][1], inv0, EPS_A);
            float a10 = fmaf(c1[j][2], inv1, EPS_A);
            float a11 = fmaf(c1[j][3], inv1, EPS_A);
            satb[cc * SATB + r0]           = __float2bfloat16(a00);
            satb[(cc + 1) * SATB + r0]     = __float2bfloat16(a01);
            satb[cc * SATB + r0 + 8]       = __float2bfloat16(a10);
            satb[(cc + 1) * SATB + r0 + 8] = __float2bfloat16(a11);
            colsum[j][0] += a00 + a10;
            colsum[j][1] += a01 + a11;
        }
        __syncthreads();

        // ---- GEMM2: S'[32,64] += attn^T[32,64] @ lnX[64,64] (ldmatrix) ----
        #pragma unroll
        for (int ks = 0; ks < 4; ks++) {
            uint32_t a0, a1, a2, a3, f0, f1, f2, f3;
            ldm_x4(a0, a1, a2, a3, aAddr + ks * 32);
            ldm_x4t(f0, f1, f2, f3, bAddr + ks * (16 * SXBU * 4));
            mma16(c2[0], a0, a1, a2, a3, f0, f1);
            mma16(c2[1], a0, a1, a2, a3, f2, f3);
            ldm_x4t(f0, f1, f2, f3, bAddr + ks * (16 * SXBU * 4) + 32);
            mma16(c2[2], a0, a1, a2, a3, f0, f1);
            mma16(c2[3], a0, a1, a2, a3, f2, f3);
        }
    }

    // ---- epilogue: deterministic per-chunk partials ----
    {
        const int crow = 16 * mblk + g;
        float* pp = &g_part[(size_t)(b * NCHUNK + chunk) * (C32 * D)];
        #pragma unroll
        for (int nb = 0; nb < 4; nb++) {
            int e0 = ncol + 8 * nb + 2 * t;
            pp[crow * D + e0]           = c2[nb][0];
            pp[crow * D + e0 + 1]       = c2[nb][1];
            pp[(crow + 8) * D + e0]     = c2[nb][2];
            pp[(crow + 8) * D + e0 + 1] = c2[nb][3];
        }
        #pragma unroll
        for (int off = 4; off < 32; off <<= 1) {
            #pragma unroll
            for (int j = 0; j < 4; j++) {
                colsum[j][0] += __shfl_xor_sync(0xffffffffu, colsum[j][0], off);
                colsum[j][1] += __shfl_xor_sync(0xffffffffu, colsum[j][1], off);
            }
        }
        __syncthreads();
        float* scs = (float*)satb;   // dead region reused: [4 warps][32]
        if (g == 0) {
            #pragma unroll
            for (int j = 0; j < 4; j++) {
                scs[w * 32 + 8 * j + 2 * t]     = colsum[j][0];
                scs[w * 32 + 8 * j + 2 * t + 1] = colsum[j][1];
            }
        }
        __syncthreads();
        if (tid < C32) {
            float s = 0.f;
            #pragma unroll
            for (int ww = 0; ww < 4; ww++) s += scs[ww * 32 + tid];
            g_sap[(b * NCHUNK + chunk) * C32 + tid] = s;
        }
    }
}

// =====================================================================
// Per-batch slot kernel (R4-proven structure). Writes bf16 Wfold.
// =====================================================================
__global__ void __launch_bounds__(256)
vslot_slots(const float* __restrict__ slots_in,
            const float* __restrict__ Wq,  const float* __restrict__ Wk,
            const float* __restrict__ Wv,
            const float* __restrict__ W_ih, const float* __restrict__ W_hh,
            const float* __restrict__ b_ih, const float* __restrict__ b_hh,
            const float* __restrict__ lns_g, const float* __restrict__ lns_b,
            const float* __restrict__ lnm_g, const float* __restrict__ lnm_b,
            const float* __restrict__ W1, const float* __restrict__ b1v,
            const float* __restrict__ W2, const float* __restrict__ b2v,
            float* __restrict__ out_slots, int first, int last)
{
    extern __shared__ float wbuf[];     // [192][65] W_ih | [192][65] W_hh
    float* wih = wbuf;
    float* whh = wbuf + 192 * 65;
    __shared__ float s_slots[NQ][D];
    __shared__ float s_upd[NQ][D];
    __shared__ float s_gx[NQ][192];
    __shared__ float s_gh[NQ][192];
    __shared__ float s_ln[NQ][D];
    __shared__ float s_hid[NQ][128];
    __shared__ float s_sax[C32][D];
    __shared__ float s_sa[C32];

    const int b = blockIdx.x;
    const int tid = threadIdx.x;

    if (first) {
        for (int i = tid; i < NQ * D; i += 256)
            (&s_slots[0][0])[i] = slots_in[b * NQ * D + i];
        __syncthreads();
    } else {
        for (int i = tid; i < C32 * D; i += 256) {
            float acc = 0.f;
            #pragma unroll
            for (int ch = 0; ch < NCHUNK; ch++)
                acc += g_part[(size_t)(b * NCHUNK + ch) * C32 * D + i];
            (&s_sax[0][0])[i] = acc;
        }
        if (tid < C32) {
            float acc = 0.f;
            #pragma unroll
            for (int ch = 0; ch < NCHUNK; ch++)
                acc += g_sap[(b * NCHUNK + ch) * C32 + tid];
            s_sa[tid] = acc;
        }
        for (int i = tid; i < NQ * D; i += 256)
            (&s_slots[0][0])[i] = g_slots[b * NQ * D + i];
        for (int i = tid; i < 192 * 64; i += 256) {
            wih[(i >> 6) * 65 + (i & 63)] = W_ih[i];
            whh[(i >> 6) * 65 + (i & 63)] = W_hh[i];
        }
        __syncthreads();

        // updates[q, h*16+dh] = (S'[c] @ Wv[:, h*16+dh]) / sa[c],  c = h*8+q
        for (int o = tid; o < NQ * D; o += 256) {
            int q = o >> 6, hd = o & 63, h = hd >> 4, c = h * 8 + q;
            float acc = 0.f;
            #pragma unroll
            for (int e = 0; e < 64; e++)
                acc = fmaf(s_sax[c][e], Wv[e * 64 + hd], acc);
            s_upd[q][hd] = acc / s_sa[c];
        }
        __syncthreads();

        // gates, fused
        for (int o = tid; o < NQ * 192; o += 256) {
            int q = o / 192, cc = o % 192;
            float gx = b_ih[cc], gh = b_hh[cc];
            const float* wr = &wih[cc * 65];
            const float* wh = &whh[cc * 65];
            #pragma unroll
            for (int dd = 0; dd < 64; dd++) {
                gx = fmaf(s_upd[q][dd],   wr[dd], gx);
                gh = fmaf(s_slots[q][dd], wh[dd], gh);
            }
            s_gx[q][cc] = gx;
            s_gh[q][cc] = gh;
        }
        __syncthreads();

        for (int o = tid; o < NQ * D; o += 256) {
            int q = o >> 6, dd = o & 63;
            float r = 1.f / (1.f + __expf(-(s_gx[q][dd]       + s_gh[q][dd])));
            float z = 1.f / (1.f + __expf(-(s_gx[q][64 + dd]  + s_gh[q][64 + dd])));
            float n = tanhf(s_gx[q][128 + dd] + r * s_gh[q][128 + dd]);
            s_upd[q][dd] = (1.f - z) * n + z * s_slots[q][dd];
        }
        __syncthreads();

        // MLP layernorm (warp per slot)
        {
            int w = tid >> 5, lane = tid & 31;
            float x0 = s_upd[w][lane], x1 = s_upd[w][lane + 32];
            float s = x0 + x1, qq = x0 * x0 + x1 * x1;
            #pragma unroll
            for (int off = 16; off; off >>= 1) {
                s  += __shfl_xor_sync(0xffffffffu, s,  off);
                qq += __shfl_xor_sync(0xffffffffu, qq, off);
            }
            float m = s * (1.f / 64.f);
            float var = qq * (1.f / 64.f) - m * m;
            float rs = rsqrtf(var + 1e-5f);
            s_ln[w][lane]      = (x0 - m) * rs * lnm_g[lane]      + lnm_b[lane];
            s_ln[w][lane + 32] = (x1 - m) * rs * lnm_g[lane + 32] + lnm_b[lane + 32];
        }
        __syncthreads();

        for (int o = tid; o < NQ * 128; o += 256) {
            int q = o >> 7, j = o & 127;
            float acc = b1v[j];
            #pragma unroll
            for (int dd = 0; dd < 64; dd++)
                acc = fmaf(s_ln[q][dd], W1[dd * 128 + j], acc);
            s_hid[q][j] = fmaxf(acc, 0.f);
        }
        __syncthreads();

        for (int o = tid; o < NQ * D; o += 256) {
            int q = o >> 6, dd = o & 63;
            float acc = b2v[dd];
            #pragma unroll
            for (int j = 0; j < 128; j++)
                acc = fmaf(s_hid[q][j], W2[j * 64 + dd], acc);
            s_slots[q][dd] = s_upd[q][dd] + acc;
        }
        __syncthreads();
    }

    for (int i = tid; i < NQ * D; i += 256)
        g_slots[b * NQ * D + i] = (&s_slots[0][0])[i];

    if (last) {
        for (int i = tid; i < NQ * D; i += 256)
            out_slots[b * NQ * D + i] = (&s_slots[0][0])[i];
    } else {
        // pre-phase: slot LN -> q = ln(slots) @ Wq -> Wfold (bf16x2)
        {
            int w = tid >> 5, lane = tid & 31;
            float x0 = s_slots[w][lane], x1 = s_slots[w][lane + 32];
            float s = x0 + x1, qq = x0 * x0 + x1 * x1;
            #pragma unroll
            for (int off = 16; off; off >>= 1) {
                s  += __shfl_xor_sync(0xffffffffu, s,  off);
                qq += __shfl_xor_sync(0xffffffffu, qq, off);
            }
            float m = s * (1.f / 64.f);
            float var = qq * (1.f / 64.f) - m * m;
            float rs = rsqrtf(var + 1e-5f);
            s_ln[w][lane]      = (x0 - m) * rs * lns_g[lane]      + lns_b[lane];
            s_ln[w][lane + 32] = (x1 - m) * rs * lns_g[lane + 32] + lns_b[lane + 32];
        }
        __syncthreads();

        for (int o = tid; o < NQ * D; o += 256) {
            int q = o >> 6, e = o & 63;
            float acc = 0.f;
            #pragma unroll
            for (int dd = 0; dd < 64; dd++)
                acc = fmaf(s_ln[q][dd], Wq[dd * 64 + e], acc);
            s_upd[q][e] = acc;
        }
        __syncthreads();

        // Wfold[c][e] = 0.25*sum_{d<16} Wk[e,h16+d]*qm[q,h16+d], packed bf16x2
        for (int o = tid; o < C32 * 32; o += 256) {
            int c = o >> 5, ep = o & 31, h = c >> 3, q = c & 7;
            float a0 = 0.f, a1 = 0.f;
            #pragma unroll
            for (int dd = 0; dd < 16; dd++) {
                float qv = s_upd[q][h * 16 + dd];
                a0 = fmaf(Wk[(2 * ep) * 64 + h * 16 + dd],     qv, a0);
                a1 = fmaf(Wk[(2 * ep + 1) * 64 + h * 16 + dd], qv, a1);
            }
            g_wfoldu[b * 1024 + c * 32 + ep] = pack_bf16x2(0.25f * a0, 0.25f * a1);
        }
    }
}

// =====================================================================
// launcher
// =====================================================================
extern "C" void kernel_launch(void* const* d_in, const int* in_sizes, int n_in,
                              void* d_out, int out_size)
{
    const float* inputs = (const float*)d_in[0];
    const float* slots  = (const float*)d_in[1];
    const float* lnin_g = (const float*)d_in[2];
    const float* lnin_b = (const float*)d_in[3];
    const float* lns_g  = (const float*)d_in[4];
    const float* lns_b  = (const float*)d_in[5];
    const float* lnm_g  = (const float*)d_in[6];
    const float* lnm_b  = (const float*)d_in[7];
    const float* Wq     = (const float*)d_in[8];
    const float* Wk     = (const float*)d_in[9];
    const float* Wv     = (const float*)d_in[10];
    const float* W_ih   = (const float*)d_in[11];
    const float* W_hh   = (const float*)d_in[12];
    const float* b_ih   = (const float*)d_in[13];
    const float* b_hh   = (const float*)d_in[14];
    const float* W1     = (const float*)d_in[15];
    const float* b1     = (const float*)d_in[16];
    const float* W2     = (const float*)d_in[17];
    const float* b2     = (const float*)d_in[18];

    float* out       = (float*)d_out;
    float* out_slots = out;                  // [64, 8, 64]
    float* out_vis   = out + B_ * NQ * D;    // [64, 8192, 8]

    // dynamic smem: 2*64*68*4 + 64*36*4 + 32*72*2 + 32*36*4 + 128*4 = 53760 B
    size_t smem = 2 * TT * SXF * 4 + TT * SXBU * 4 + C32 * SATB * 2
                + C32 * WFU * 4 + 128 * 4;
    cudaFuncSetAttribute(vslot_main,
                         cudaFuncAttributeMaxDynamicSharedMemorySize, (int)smem);
    size_t smem_s = (size_t)(2 * 192 * 65) * sizeof(float);
    cudaFuncSetAttribute(vslot_slots,
                         cudaFuncAttributeMaxDynamicSharedMemorySize, (int)smem_s);

#define SLOT_K(first, last)                                                     \
    vslot_slots<<<B_, 256, smem_s>>>(slots, Wq, Wk, Wv, W_ih, W_hh, b_ih, b_hh,  \
                             lns_g, lns_b, lnm_g, lnm_b, W1, b1, W2, b2,         \
                             out_slots, (first), (last))

    SLOT_K(1, 0);                                                        // init + Wfold0
    vslot_main<<<B_ * NCHUNK, 128, smem>>>(inputs, lnin_g, lnin_b, out_vis, 0);
    SLOT_K(0, 0);                                                        // post0 + pre1
    vslot_main<<<B_ * NCHUNK, 128, smem>>>(inputs, lnin_g, lnin_b, out_vis, 0);
    SLOT_K(0, 0);                                                        // post1 + pre2
    vslot_main<<<B_ * NCHUNK, 128, smem>>>(inputs, lnin_g, lnin_b, out_vis, 1);
    SLOT_K(0, 1);                                                        // post2 -> out
#undef SLOT_K
}